// round 3
// baseline (speedup 1.0000x reference)
#include <cuda_runtime.h>
#include <cuda_bf16.h>
#include <stdint.h>

#define MAX_NODES 100000
#define OUT_CH    32
#define CAP       128          // per-row bin capacity (max degree ~60-65 expected)
#define OVF_CAP   65536        // overflow list capacity (safety net, expect 0 used)

// Scratch (__device__ globals; no cudaMalloc allowed)
__device__ float g_Wt[MAX_NODES * OUT_CH];                 // 12.8 MB transposed W
__device__ int   g_count[MAX_NODES];                       // per-raw-row degree
__device__ int   g_bin[(size_t)MAX_NODES * CAP];           // 51.2 MB col bins
__device__ int   g_ovf[2 * OVF_CAP];                       // overflow (row,col) pairs
__device__ int   g_ovf_cnt;
__device__ int   g_rowmin;

// ---------------------------------------------------------------------------
// K1: zero per-row counters, reset rowmin + overflow counter.
// ---------------------------------------------------------------------------
__global__ void init_kernel(int N) {
    int i = blockIdx.x * blockDim.x + threadIdx.x;
    if (i == 0) { g_rowmin = 0x7fffffff; g_ovf_cnt = 0; }
    if (i < N) g_count[i] = 0;
}

// ---------------------------------------------------------------------------
// K2: g_rowmin = min over edge_index[0, :].
// ---------------------------------------------------------------------------
__global__ void rowmin_kernel(const int* __restrict__ rows, int E) {
    int i = blockIdx.x * blockDim.x + threadIdx.x;
    int stride = gridDim.x * blockDim.x;
    int m = 0x7fffffff;
    for (; i < E; i += stride) m = min(m, __ldg(&rows[i]));
    #pragma unroll
    for (int off = 16; off > 0; off >>= 1)
        m = min(m, __shfl_xor_sync(0xffffffffu, m, off));
    if ((threadIdx.x & 31) == 0) atomicMin(&g_rowmin, m);
}

// ---------------------------------------------------------------------------
// K3: transpose W[32, N] -> Wt[N, 32] (coalesced reads per channel).
// ---------------------------------------------------------------------------
__global__ void transpose_kernel(const float* __restrict__ W, int N) {
    int n = blockIdx.x * blockDim.x + threadIdx.x;
    if (n >= N) return;
    float v[OUT_CH];
    #pragma unroll
    for (int c = 0; c < OUT_CH; c++)
        v[c] = __ldg(&W[(size_t)c * N + n]);
    float4* dst = reinterpret_cast<float4*>(&g_Wt[(size_t)n * OUT_CH]);
    #pragma unroll
    for (int j = 0; j < OUT_CH / 4; j++)
        dst[j] = make_float4(v[4*j+0], v[4*j+1], v[4*j+2], v[4*j+3]);
}

// ---------------------------------------------------------------------------
// K4: bucket edges by raw row. One thread per edge; scalar histogram atomic
// yields the slot; cols land contiguously per row (int4-readable later).
// ---------------------------------------------------------------------------
__global__ void fill_kernel(const int* __restrict__ ei, int E) {
    int e = blockIdx.x * blockDim.x + threadIdx.x;
    if (e >= E) return;
    int row = __ldg(&ei[e]);
    int col = __ldg(&ei[E + e]);
    int c = atomicAdd(&g_count[row], 1);
    if (c < CAP) {
        g_bin[(size_t)row * CAP + c] = col;
    } else {
        int idx = atomicAdd(&g_ovf_cnt, 1);
        if (idx < OVF_CAP) { g_ovf[2*idx] = row; g_ovf[2*idx+1] = col; }
    }
}

// ---------------------------------------------------------------------------
// K5: pull-gather. One warp per OUTPUT row n; sums Wt rows of its bin
// (raw row = n + rowmin), lane = channel. No atomics.
// ---------------------------------------------------------------------------
__global__ void gather_kernel(float* __restrict__ out, const float* __restrict__ b,
                              int N) {
    int warp = (int)((blockIdx.x * blockDim.x + threadIdx.x) >> 5);
    int lane = threadIdx.x & 31;
    if (warp >= N) return;
    int raw = warp + g_rowmin;
    float acc = 0.f;
    if (raw < N) {
        int cnt = min(g_count[raw], CAP);
        const int* bb = &g_bin[(size_t)raw * CAP];
        int i = 0;
        for (; i + 4 <= cnt; i += 4) {
            int4 c4 = *reinterpret_cast<const int4*>(bb + i);   // broadcast load
            float a0 = __ldg(&g_Wt[(size_t)c4.x * OUT_CH + lane]);
            float a1 = __ldg(&g_Wt[(size_t)c4.y * OUT_CH + lane]);
            float a2 = __ldg(&g_Wt[(size_t)c4.z * OUT_CH + lane]);
            float a3 = __ldg(&g_Wt[(size_t)c4.w * OUT_CH + lane]);
            acc += (a0 + a1) + (a2 + a3);
        }
        for (; i < cnt; i++)
            acc += __ldg(&g_Wt[(size_t)bb[i] * OUT_CH + lane]);
    }
    out[(size_t)warp * OUT_CH + lane] = acc + __ldg(&b[lane]);
}

// ---------------------------------------------------------------------------
// K6: overflow fixup (runs AFTER gather wrote out; expected empty).
// ---------------------------------------------------------------------------
__global__ void ovf_kernel(float* __restrict__ out, int N) {
    int minr = g_rowmin;
    int cnt = min(g_ovf_cnt, OVF_CAP);
    int tid = blockIdx.x * blockDim.x + threadIdx.x;
    int stride = gridDim.x * blockDim.x;
    for (int idx = tid; idx < cnt * 8; idx += stride) {
        int e = idx >> 3, t = idx & 7;
        int row = g_ovf[2*e] - minr;
        int col = g_ovf[2*e + 1];
        if ((unsigned)row >= (unsigned)N) continue;
        const float4 v = *reinterpret_cast<const float4*>(&g_Wt[(size_t)col * OUT_CH + t * 4]);
        float* dst = &out[(size_t)row * OUT_CH + t * 4];
        asm volatile("red.global.add.v4.f32 [%0], {%1, %2, %3, %4};"
                     :: "l"(dst), "f"(v.x), "f"(v.y), "f"(v.z), "f"(v.w)
                     : "memory");
    }
}

// ---------------------------------------------------------------------------
extern "C" void kernel_launch(void* const* d_in, const int* in_sizes, int n_in,
                              void* d_out, int out_size) {
    const int*   ei = (const int*)d_in[0];     // [2, E] indices (stored int32)
    const float* W  = (const float*)d_in[1];   // [32, N]
    const float* b  = (const float*)d_in[2];   // [32]
    float* out = (float*)d_out;                // [N, 32]

    int E = in_sizes[0] / 2;
    int N = in_sizes[1] / OUT_CH;

    { // K1: init counters
        int threads = 256, blocks = (N + threads - 1) / threads;
        init_kernel<<<blocks, threads>>>(N);
    }
    { // K2: row min
        rowmin_kernel<<<1024, 256>>>(ei, E);
    }
    { // K3: transpose
        int threads = 256, blocks = (N + threads - 1) / threads;
        transpose_kernel<<<blocks, threads>>>(W, N);
    }
    { // K4: bucket edges
        int threads = 256, blocks = (E + threads - 1) / threads;
        fill_kernel<<<blocks, threads>>>(ei, E);
    }
    { // K5: pull-gather (1 warp per row)
        int threads = 256;
        long long tw = (long long)N * 32;
        int blocks = (int)((tw + threads - 1) / threads);
        gather_kernel<<<blocks, threads>>>(out, b, N);
    }
    { // K6: overflow fixup
        ovf_kernel<<<64, 256>>>(out, N);
    }
}

// round 4
// speedup vs baseline: 1.2953x; 1.2953x over previous
#include <cuda_runtime.h>
#include <cuda_bf16.h>
#include <stdint.h>

#define OUT_CH 32
#define MAX_NODES 100000

__device__ float g_Wt[MAX_NODES * OUT_CH];   // transposed W, L2-resident 12.8 MB
__device__ int   g_rowmin;

// ---------------------------------------------------------------------------
// K0: tiny reset (must precede prep's atomicMin).
// ---------------------------------------------------------------------------
__global__ void reset_kernel() {
    if (threadIdx.x == 0) g_rowmin = 0x7fffffff;
}

// ---------------------------------------------------------------------------
// K1 (fused prep): blocks [0, NB): transpose W[32,N]->Wt[N,32] and out[n,:]=b.
//                  blocks [NB, NB+64): grid-stride row-min over edge rows.
// ---------------------------------------------------------------------------
__global__ void prep_kernel(const float* __restrict__ W, const float* __restrict__ b,
                            const int* __restrict__ rows, float* __restrict__ out,
                            int N, int E, int NB) {
    if ((int)blockIdx.x < NB) {
        int n = blockIdx.x * blockDim.x + threadIdx.x;
        if (n >= N) return;
        float v[OUT_CH];
        #pragma unroll
        for (int c = 0; c < OUT_CH; c++)
            v[c] = __ldg(&W[(size_t)c * N + n]);
        float4* dst = reinterpret_cast<float4*>(&g_Wt[(size_t)n * OUT_CH]);
        #pragma unroll
        for (int j = 0; j < OUT_CH / 4; j++)
            dst[j] = make_float4(v[4*j+0], v[4*j+1], v[4*j+2], v[4*j+3]);
        // out[n, :] = b
        float4* o = reinterpret_cast<float4*>(&out[(size_t)n * OUT_CH]);
        #pragma unroll
        for (int j = 0; j < OUT_CH / 4; j++) {
            float4 bv = __ldg(reinterpret_cast<const float4*>(b) + j);
            o[j] = bv;
        }
    } else {
        int slot = (blockIdx.x - NB) * blockDim.x + threadIdx.x;
        int stride = 64 * blockDim.x;
        int m = 0x7fffffff;
        for (int i = slot; i < E; i += stride)
            m = min(m, __ldg(&rows[i]));
        #pragma unroll
        for (int off = 16; off > 0; off >>= 1)
            m = min(m, __shfl_xor_sync(0xffffffffu, m, off));
        if ((threadIdx.x & 31) == 0) atomicMin(&g_rowmin, m);
    }
}

// ---------------------------------------------------------------------------
// K2: scatter. 8 threads per edge-pair slot; each thread handles channel-quad t
// of TWO independent edges (e, e+half) -> 2 independent LDG->RED chains.
// ---------------------------------------------------------------------------
__global__ void scatter_kernel(const int* __restrict__ ei, int E, int N,
                               float* __restrict__ out) {
    int half = (E + 1) >> 1;
    long long gtid = (long long)blockIdx.x * blockDim.x + threadIdx.x;
    long long g = gtid >> 3;
    int t = (int)(gtid & 7);
    if (g >= half) return;
    int minr = g_rowmin;

    int e0 = (int)g;
    int e1 = e0 + half;
    bool has1 = (e1 < E);

    // front-load all index reads (independent)
    int row0 = __ldg(&ei[e0]);
    int col0 = __ldg(&ei[E + e0]);
    int row1 = has1 ? __ldg(&ei[e1]) : 0;
    int col1 = has1 ? __ldg(&ei[E + e1]) : 0;

    row0 -= minr;  row1 -= minr;
    bool ok0 = (unsigned)row0 < (unsigned)N && (unsigned)col0 < (unsigned)N;
    bool ok1 = has1 && (unsigned)row1 < (unsigned)N && (unsigned)col1 < (unsigned)N;

    // independent gathers (both in flight)
    float4 v0, v1;
    if (ok0) v0 = __ldg(reinterpret_cast<const float4*>(&g_Wt[(size_t)col0 * OUT_CH]) + t);
    if (ok1) v1 = __ldg(reinterpret_cast<const float4*>(&g_Wt[(size_t)col1 * OUT_CH]) + t);

    if (ok0) {
        float* dst = &out[(size_t)row0 * OUT_CH + t * 4];
        asm volatile("red.global.add.v4.f32 [%0], {%1, %2, %3, %4};"
                     :: "l"(dst), "f"(v0.x), "f"(v0.y), "f"(v0.z), "f"(v0.w)
                     : "memory");
    }
    if (ok1) {
        float* dst = &out[(size_t)row1 * OUT_CH + t * 4];
        asm volatile("red.global.add.v4.f32 [%0], {%1, %2, %3, %4};"
                     :: "l"(dst), "f"(v1.x), "f"(v1.y), "f"(v1.z), "f"(v1.w)
                     : "memory");
    }
}

// ---------------------------------------------------------------------------
extern "C" void kernel_launch(void* const* d_in, const int* in_sizes, int n_in,
                              void* d_out, int out_size) {
    const int*   ei = (const int*)d_in[0];     // [2, E]
    const float* W  = (const float*)d_in[1];   // [32, N]
    const float* b  = (const float*)d_in[2];   // [32]
    float* out = (float*)d_out;                // [N, 32]

    int E = in_sizes[0] / 2;
    int N = in_sizes[1] / OUT_CH;

    reset_kernel<<<1, 32>>>();

    int threads = 256;
    int NB = (N + threads - 1) / threads;
    prep_kernel<<<NB + 64, threads>>>(W, b, ei, out, N, E, NB);

    long long half = (E + 1) >> 1;
    long long work = half * 8;
    int blocks = (int)((work + threads - 1) / threads);
    scatter_kernel<<<blocks, threads>>>(ei, E, N, out);
}